// round 3
// baseline (speedup 1.0000x reference)
#include <cuda_runtime.h>
#include <stdint.h>

// Problem constants
#define NN 50000
#define EE 600000
#define FF 128
#define HH 128
#define OO 64
#define RR 8
#define KT (RR * FF)    // 1024
#define KTOT (KT + FF)  // 1152
#define BB (NN * RR)    // 400000 buckets (dst, rel)
#define NB ((BB + 1023) / 1024)  // 391 scan blocks

// ---------------------------------------------------------------------------
// Device scratch
// ---------------------------------------------------------------------------
__device__ float    g_T[(size_t)NN * KT];   // 204.8 MB aggregation target
__device__ float    g_h[(size_t)NN * HH];   // layer-1 output
__device__ int      g_bcnt[BB];             // per-(dst,rel) histogram
__device__ int      g_bcur[BB];             // reorder cursors
__device__ int      g_boff[BB + 1];         // exclusive offsets
__device__ int      g_part[512];            // scan block partials
__device__ int      g_esrc[EE];             // sorted edge: source node
__device__ float    g_ecoef[EE];            // sorted edge: coef (norm ew * inv_cnt)
__device__ float    g_inv[NN];
__device__ unsigned g_mm[2];                // min/max bits of edge_weight
__device__ int      g_is64;

// ---------------------------------------------------------------------------
// Helpers
// ---------------------------------------------------------------------------
__device__ __forceinline__ int load_idx(const void* p, size_t i) {
    return g_is64 ? (int)((const long long*)p)[i] : ((const int*)p)[i];
}
__device__ __forceinline__ void fma2(unsigned long long& d,
                                     unsigned long long a,
                                     unsigned long long b) {
    asm("fma.rn.f32x2 %0, %1, %2, %0;" : "+l"(d) : "l"(a), "l"(b));
}
__device__ __forceinline__ unsigned long long swap64(unsigned long long v) {
    return (v >> 32) | (v << 32);
}
__device__ __forceinline__ float lo32(unsigned long long v) {
    return __uint_as_float((unsigned)v);
}
__device__ __forceinline__ float hi32(unsigned long long v) {
    return __uint_as_float((unsigned)(v >> 32));
}

__global__ void k_detect(const void* ei) {
    const int* p = (const int*)ei;
    int nz = 0;
    for (int i = 1; i < 2001; i += 2) nz |= p[i];
    g_is64 = (nz == 0) ? 1 : 0;
}

__global__ void k_zero() {
    int i = blockIdx.x * blockDim.x + threadIdx.x;
    for (int j = i; j < BB; j += gridDim.x * blockDim.x) {
        g_bcnt[j] = 0; g_bcur[j] = 0;
    }
    if (i == 0) { g_mm[0] = 0xFFFFFFFFu; g_mm[1] = 0u; }
}

// Histogram over (dst, rel) + edge-weight min/max.
__global__ void k_hist(const void* __restrict__ ei,
                       const float* __restrict__ ew,
                       const void* __restrict__ et) {
    __shared__ unsigned smn, smx;
    if (threadIdx.x == 0) { smn = 0xFFFFFFFFu; smx = 0u; }
    __syncthreads();
    unsigned mn = 0xFFFFFFFFu, mx = 0u;
    for (int e = blockIdx.x * blockDim.x + threadIdx.x; e < EE;
         e += gridDim.x * blockDim.x) {
        unsigned b = __float_as_uint(ew[e]);
        mn = min(mn, b); mx = max(mx, b);
        int dst = load_idx(ei, (size_t)EE + e);
        int r   = load_idx(et, e);
        atomicAdd(&g_bcnt[dst * RR + r], 1);
    }
    #pragma unroll
    for (int o = 16; o; o >>= 1) {
        mn = min(mn, __shfl_xor_sync(0xFFFFFFFFu, mn, o));
        mx = max(mx, __shfl_xor_sync(0xFFFFFFFFu, mx, o));
    }
    if ((threadIdx.x & 31) == 0) { atomicMin(&smn, mn); atomicMax(&smx, mx); }
    __syncthreads();
    if (threadIdx.x == 0) { atomicMin(&g_mm[0], smn); atomicMax(&g_mm[1], smx); }
}

// Two-level exclusive scan of g_bcnt -> g_boff.
__global__ void k_scan1() {
    __shared__ int s[1024];
    int i = blockIdx.x * 1024 + threadIdx.x;
    int v = (i < BB) ? g_bcnt[i] : 0;
    s[threadIdx.x] = v;
    __syncthreads();
    for (int o = 1; o < 1024; o <<= 1) {
        int t = (threadIdx.x >= o) ? s[threadIdx.x - o] : 0;
        __syncthreads();
        s[threadIdx.x] += t;
        __syncthreads();
    }
    if (i < BB) g_boff[i] = s[threadIdx.x] - v;  // block-local exclusive
    if (threadIdx.x == 1023) g_part[blockIdx.x] = s[1023];
}
__global__ void k_scan2() {
    __shared__ int s[512];
    int v = (threadIdx.x < NB) ? g_part[threadIdx.x] : 0;
    s[threadIdx.x] = v;
    __syncthreads();
    for (int o = 1; o < 512; o <<= 1) {
        int t = (threadIdx.x >= o) ? s[threadIdx.x - o] : 0;
        __syncthreads();
        s[threadIdx.x] += t;
        __syncthreads();
    }
    if (threadIdx.x < NB) g_part[threadIdx.x] = s[threadIdx.x] - v;
}
__global__ void k_scan3() {
    int i = blockIdx.x * blockDim.x + threadIdx.x;
    for (int j = i; j < BB; j += gridDim.x * blockDim.x)
        g_boff[j] += g_part[j >> 10];
    if (i == 0) g_boff[BB] = EE;
}

// 1 / in-degree from bucket offsets.
__global__ void k_inv() {
    int d = blockIdx.x * blockDim.x + threadIdx.x;
    if (d < NN) {
        int c = g_boff[d * RR + RR] - g_boff[d * RR];
        g_inv[d] = 1.0f / (float)max(c, 1);
    }
}

// Counting-sort reorder; fold normalized edge weight * inv_cnt into coef.
__global__ void k_reorder(const void* __restrict__ ei,
                          const float* __restrict__ ew,
                          const void* __restrict__ et) {
    float mn = __uint_as_float(g_mm[0]);
    float mx = __uint_as_float(g_mm[1]);
    float sc = 1.0f / (mx - mn + 1e-8f);
    for (int e = blockIdx.x * blockDim.x + threadIdx.x; e < EE;
         e += gridDim.x * blockDim.x) {
        int src = load_idx(ei, e);
        int dst = load_idx(ei, (size_t)EE + e);
        int r   = load_idx(et, e);
        int key = dst * RR + r;
        int pos = g_boff[key] + atomicAdd(&g_bcur[key], 1);
        g_esrc[pos]  = src;
        g_ecoef[pos] = (ew[e] - mn) * sc * g_inv[dst];
    }
}

// Aggregation: one warp per dst node. For each relation run, gather x[src]
// rows and accumulate in registers; write the T row exactly once.
__global__ void k_agg(const float* __restrict__ X) {
    int w = (blockIdx.x * blockDim.x + threadIdx.x) >> 5;
    int lane = threadIdx.x & 31;
    if (w >= NN) return;
    int base = w * RR;
    float* trow = g_T + (size_t)w * KT + lane * 4;
    #pragma unroll
    for (int r = 0; r < RR; r++) {
        int s0 = g_boff[base + r], s1 = g_boff[base + r + 1];
        float4 acc = make_float4(0.f, 0.f, 0.f, 0.f);
        for (int e = s0; e < s1; e++) {
            float c = g_ecoef[e];
            int src = g_esrc[e];
            float4 xv = *(const float4*)(X + (size_t)src * FF + lane * 4);
            acc.x += c * xv.x; acc.y += c * xv.y;
            acc.z += c * xv.z; acc.w += c * xv.w;
        }
        *(float4*)(trow + r * FF) = acc;
    }
}

// ---------------------------------------------------------------------------
// Fused GEMM with packed fp32x2 FMA (unchanged from round 2).
// ---------------------------------------------------------------------------
template <int BN, int TN, bool RELU>
__global__ void __launch_bounds__(256, 2)
k_gemm(const float* __restrict__ A0, const float* __restrict__ W,
       const float* __restrict__ X, const float* __restrict__ Rt,
       const float* __restrict__ bias, float* __restrict__ out) {
    const int BM = 128, BK = 8;
    const int JP = TN / 2;
    __shared__ __align__(16) float As[BK][BM];
    __shared__ __align__(16) float Bs[BK][BN];
    int tid = threadIdx.x;
    int tx = tid & 15, ty = tid >> 4;
    int row0 = blockIdx.x * BM;

    unsigned long long accN[4][JP], accX[4][JP];
    #pragma unroll
    for (int i = 0; i < 4; i++)
        #pragma unroll
        for (int j = 0; j < JP; j++) { accN[i][j] = 0ull; accX[i][j] = 0ull; }

    int arow = tid >> 1, acol = (tid & 1) * 4;
    int n_a = row0 + arow;
    bool avalid = (n_a < NN);

    for (int k0 = 0; k0 < KTOT; k0 += BK) {
        int ka = k0 + acol;
        float4 av = make_float4(0.f, 0.f, 0.f, 0.f);
        if (avalid) {
            const float* ap = (ka < KT)
                ? (A0 + (size_t)n_a * KT + ka)
                : (X + (size_t)n_a * FF + (ka - KT));
            av = *(const float4*)ap;
        }
        As[acol + 0][arow] = av.x; As[acol + 1][arow] = av.y;
        As[acol + 2][arow] = av.z; As[acol + 3][arow] = av.w;
        if (BN == 128) {
            int brow = tid >> 5, bcol = (tid & 31) * 4;
            int kb = k0 + brow;
            const float* bp = (kb < KT) ? (W + (size_t)kb * BN + bcol)
                                        : (Rt + (size_t)(kb - KT) * BN + bcol);
            *(float4*)&Bs[brow][bcol] = *(const float4*)bp;
        } else {
            int brow = tid >> 5, bcol = (tid & 31) * 2;
            int kb = k0 + brow;
            const float* bp = (kb < KT) ? (W + (size_t)kb * BN + bcol)
                                        : (Rt + (size_t)(kb - KT) * BN + bcol);
            *(float2*)&Bs[brow][bcol] = *(const float2*)bp;
        }
        __syncthreads();

        #pragma unroll
        for (int kk = 0; kk < BK; kk++) {
            ulonglong2 a01 = *(ulonglong2*)&As[kk][ty * 8];
            ulonglong2 a23 = *(ulonglong2*)&As[kk][ty * 8 + 4];
            unsigned long long A[4] = {a01.x, a01.y, a23.x, a23.y};
            unsigned long long B[JP], S[JP];
            if (TN == 8) {
                ulonglong2 b01 = *(ulonglong2*)&Bs[kk][tx * TN];
                ulonglong2 b23 = *(ulonglong2*)&Bs[kk][tx * TN + 4];
                B[0] = b01.x; B[1] = b01.y; B[2] = b23.x; B[3] = b23.y;
            } else {
                ulonglong2 b01 = *(ulonglong2*)&Bs[kk][tx * TN];
                B[0] = b01.x; B[1] = b01.y;
            }
            #pragma unroll
            for (int jp = 0; jp < JP; jp++) S[jp] = swap64(B[jp]);
            #pragma unroll
            for (int ip = 0; ip < 4; ip++)
                #pragma unroll
                for (int jp = 0; jp < JP; jp++) {
                    fma2(accN[ip][jp], A[ip], B[jp]);
                    fma2(accX[ip][jp], A[ip], S[jp]);
                }
        }
        __syncthreads();
    }

    float c[8][TN];
    #pragma unroll
    for (int ip = 0; ip < 4; ip++)
        #pragma unroll
        for (int jp = 0; jp < JP; jp++) {
            c[2 * ip + 0][2 * jp + 0] = lo32(accN[ip][jp]);
            c[2 * ip + 1][2 * jp + 1] = hi32(accN[ip][jp]);
            c[2 * ip + 0][2 * jp + 1] = lo32(accX[ip][jp]);
            c[2 * ip + 1][2 * jp + 0] = hi32(accX[ip][jp]);
        }

    #pragma unroll
    for (int i = 0; i < 8; i++) {
        int n = row0 + ty * 8 + i;
        if (n >= NN) continue;
        #pragma unroll
        for (int j = 0; j < TN; j += 4) {
            int h = tx * TN + j;
            float4 v;
            v.x = c[i][j + 0] + bias[h + 0];
            v.y = c[i][j + 1] + bias[h + 1];
            v.z = c[i][j + 2] + bias[h + 2];
            v.w = c[i][j + 3] + bias[h + 3];
            if (RELU) {
                v.x = fmaxf(v.x, 0.f); v.y = fmaxf(v.y, 0.f);
                v.z = fmaxf(v.z, 0.f); v.w = fmaxf(v.w, 0.f);
            }
            *(float4*)(out + (size_t)n * BN + h) = v;
        }
    }
}

// ---------------------------------------------------------------------------
// Launch
// ---------------------------------------------------------------------------
extern "C" void kernel_launch(void* const* d_in, const int* in_sizes, int n_in,
                              void* d_out, int out_size) {
    const float* x     = (const float*)d_in[0];
    const void*  ei    = d_in[1];
    const float* ew    = (const float*)d_in[2];
    const void*  et    = d_in[3];
    const float* W1    = (const float*)d_in[4];
    const float* root1 = (const float*)d_in[5];
    const float* bias1 = (const float*)d_in[6];
    const float* W2    = (const float*)d_in[7];
    const float* root2 = (const float*)d_in[8];
    const float* bias2 = (const float*)d_in[9];
    float* out = (float*)d_out;

    void *pT = nullptr, *ph = nullptr;
    cudaGetSymbolAddress(&pT, g_T);
    cudaGetSymbolAddress(&ph, g_h);
    const float* Tp = (const float*)pT;
    float*       hp = (float*)ph;

    // One-time edge preprocessing (counting sort by (dst, rel))
    k_detect<<<1, 1>>>(ei);
    k_zero<<<512, 256>>>();
    k_hist<<<1024, 256>>>(ei, ew, et);
    k_scan1<<<NB, 1024>>>();
    k_scan2<<<1, 512>>>();
    k_scan3<<<512, 256>>>();
    k_inv<<<(NN + 255) / 256, 256>>>();
    k_reorder<<<1024, 256>>>(ei, ew, et);

    // ---- layer 1 ----
    k_agg<<<(NN * 32 + 255) / 256, 256>>>(x);
    k_gemm<128, 8, true><<<(NN + 127) / 128, 256>>>(Tp, W1, x, root1, bias1, hp);

    // ---- layer 2 ----
    k_agg<<<(NN * 32 + 255) / 256, 256>>>(hp);
    k_gemm<64, 4, false><<<(NN + 127) / 128, 256>>>(Tp, W2, hp, root2, bias2, out);
}

// round 4
// speedup vs baseline: 1.2415x; 1.2415x over previous
#include <cuda_runtime.h>
#include <stdint.h>

// Problem constants
#define NN 50000
#define EE 600000
#define FF 128
#define HH 128
#define OO 64
#define RR 8
#define KT (RR * FF)   // 1024 = flattened (relation, feature) K dim
#define KTOT (KT + FF) // 1152 = + root-transform K

// ---------------------------------------------------------------------------
// Device scratch
// ---------------------------------------------------------------------------
__device__ float    g_T[(size_t)NN * KT];   // 204.8 MB scatter accumulator
__device__ float    g_h[(size_t)NN * HH];   // 25.6 MB layer-1 output
__device__ int      g_cnt[NN];
__device__ float    g_inv[NN];
__device__ unsigned g_mm[2];                // min/max bits of edge_weight
__device__ int      g_is64;                 // 1 if indices are int64

// ---------------------------------------------------------------------------
// Helpers
// ---------------------------------------------------------------------------
__device__ __forceinline__ int load_idx(const void* p, size_t i) {
    return g_is64 ? (int)((const long long*)p)[i] : ((const int*)p)[i];
}
__device__ __forceinline__ void fma2(unsigned long long& d,
                                     unsigned long long a,
                                     unsigned long long b) {
    asm("fma.rn.f32x2 %0, %1, %2, %0;" : "+l"(d) : "l"(a), "l"(b));
}
__device__ __forceinline__ unsigned long long swap64(unsigned long long v) {
    return (v >> 32) | (v << 32);
}
__device__ __forceinline__ float lo32(unsigned long long v) {
    return __uint_as_float((unsigned)v);
}
__device__ __forceinline__ float hi32(unsigned long long v) {
    return __uint_as_float((unsigned)(v >> 32));
}

// Detect index dtype: int64 values < 2^31 have zero odd 32-bit words.
__global__ void k_detect(const void* ei) {
    const int* p = (const int*)ei;
    int nz = 0;
    for (int i = 1; i < 2001; i += 2) nz |= p[i];
    g_is64 = (nz == 0) ? 1 : 0;
}

__global__ void k_zero_cnt() {
    int i = blockIdx.x * blockDim.x + threadIdx.x;
    if (i < NN) g_cnt[i] = 0;
    if (i == 0) { g_mm[0] = 0xFFFFFFFFu; g_mm[1] = 0u; }
}

// One pass over edges: min/max of edge_weight + in-degree counts.
__global__ void k_edge_stats(const void* __restrict__ ei,
                             const float* __restrict__ ew) {
    __shared__ unsigned smn, smx;
    if (threadIdx.x == 0) { smn = 0xFFFFFFFFu; smx = 0u; }
    __syncthreads();
    unsigned mn = 0xFFFFFFFFu, mx = 0u;
    for (int e = blockIdx.x * blockDim.x + threadIdx.x; e < EE;
         e += gridDim.x * blockDim.x) {
        unsigned b = __float_as_uint(ew[e]);
        mn = min(mn, b); mx = max(mx, b);
        int dst = load_idx(ei, (size_t)EE + e);
        atomicAdd(&g_cnt[dst], 1);
    }
    #pragma unroll
    for (int o = 16; o; o >>= 1) {
        mn = min(mn, __shfl_xor_sync(0xFFFFFFFFu, mn, o));
        mx = max(mx, __shfl_xor_sync(0xFFFFFFFFu, mx, o));
    }
    if ((threadIdx.x & 31) == 0) { atomicMin(&smn, mn); atomicMax(&smx, mx); }
    __syncthreads();
    if (threadIdx.x == 0) { atomicMin(&g_mm[0], smn); atomicMax(&g_mm[1], smx); }
}

__global__ void k_inv() {
    int i = blockIdx.x * blockDim.x + threadIdx.x;
    if (i < NN) g_inv[i] = 1.0f / (float)max(g_cnt[i], 1);
}

// Scatter: one warp per edge. T[dst, et, :] += coef * X[src, :]
// Each lane covers 4 consecutive floats with ONE red.global.add.v4.f32
// (16B vector reduction, sm_90+): 1 RED instruction per warp per edge
// instead of 4 -> 4x fewer REDG issues.
__global__ void k_scatter(const float* __restrict__ X,
                          const void* __restrict__ ei,
                          const float* __restrict__ ew,
                          const void* __restrict__ et) {
    int e = (blockIdx.x * blockDim.x + threadIdx.x) >> 5;
    int lane = threadIdx.x & 31;
    if (e >= EE) return;
    int src = load_idx(ei, e);
    int dst = load_idx(ei, (size_t)EE + e);
    int r   = load_idx(et, e);
    float mn = __uint_as_float(g_mm[0]);
    float mx = __uint_as_float(g_mm[1]);
    float coef = (ew[e] - mn) / (mx - mn + 1e-8f) * g_inv[dst];
    const float* xr = X + (size_t)src * FF + lane * 4;
    float* tr = g_T + ((size_t)dst * RR + r) * FF + lane * 4;
    float4 xv = *(const float4*)xr;
    asm volatile("red.global.add.v4.f32 [%0], {%1, %2, %3, %4};"
                 :: "l"(tr),
                    "f"(coef * xv.x), "f"(coef * xv.y),
                    "f"(coef * xv.z), "f"(coef * xv.w)
                 : "memory");
}

// ---------------------------------------------------------------------------
// Fused GEMM with packed fp32x2 FMA (unchanged).
// ---------------------------------------------------------------------------
template <int BN, int TN, bool RELU>
__global__ void __launch_bounds__(256, 2)
k_gemm(const float* __restrict__ A0, const float* __restrict__ W,
       const float* __restrict__ X, const float* __restrict__ Rt,
       const float* __restrict__ bias, float* __restrict__ out) {
    const int BM = 128, BK = 8;
    const int JP = TN / 2;
    __shared__ __align__(16) float As[BK][BM];
    __shared__ __align__(16) float Bs[BK][BN];
    int tid = threadIdx.x;
    int tx = tid & 15, ty = tid >> 4;
    int row0 = blockIdx.x * BM;

    unsigned long long accN[4][JP], accX[4][JP];
    #pragma unroll
    for (int i = 0; i < 4; i++)
        #pragma unroll
        for (int j = 0; j < JP; j++) { accN[i][j] = 0ull; accX[i][j] = 0ull; }

    int arow = tid >> 1, acol = (tid & 1) * 4;
    int n_a = row0 + arow;
    bool avalid = (n_a < NN);

    for (int k0 = 0; k0 < KTOT; k0 += BK) {
        int ka = k0 + acol;
        float4 av = make_float4(0.f, 0.f, 0.f, 0.f);
        if (avalid) {
            const float* ap = (ka < KT)
                ? (A0 + (size_t)n_a * KT + ka)
                : (X + (size_t)n_a * FF + (ka - KT));
            av = *(const float4*)ap;
        }
        As[acol + 0][arow] = av.x; As[acol + 1][arow] = av.y;
        As[acol + 2][arow] = av.z; As[acol + 3][arow] = av.w;
        if (BN == 128) {
            int brow = tid >> 5, bcol = (tid & 31) * 4;
            int kb = k0 + brow;
            const float* bp = (kb < KT) ? (W + (size_t)kb * BN + bcol)
                                        : (Rt + (size_t)(kb - KT) * BN + bcol);
            *(float4*)&Bs[brow][bcol] = *(const float4*)bp;
        } else {
            int brow = tid >> 5, bcol = (tid & 31) * 2;
            int kb = k0 + brow;
            const float* bp = (kb < KT) ? (W + (size_t)kb * BN + bcol)
                                        : (Rt + (size_t)(kb - KT) * BN + bcol);
            *(float2*)&Bs[brow][bcol] = *(const float2*)bp;
        }
        __syncthreads();

        #pragma unroll
        for (int kk = 0; kk < BK; kk++) {
            ulonglong2 a01 = *(ulonglong2*)&As[kk][ty * 8];
            ulonglong2 a23 = *(ulonglong2*)&As[kk][ty * 8 + 4];
            unsigned long long A[4] = {a01.x, a01.y, a23.x, a23.y};
            unsigned long long B[JP], S[JP];
            if (TN == 8) {
                ulonglong2 b01 = *(ulonglong2*)&Bs[kk][tx * TN];
                ulonglong2 b23 = *(ulonglong2*)&Bs[kk][tx * TN + 4];
                B[0] = b01.x; B[1] = b01.y; B[2] = b23.x; B[3] = b23.y;
            } else {
                ulonglong2 b01 = *(ulonglong2*)&Bs[kk][tx * TN];
                B[0] = b01.x; B[1] = b01.y;
            }
            #pragma unroll
            for (int jp = 0; jp < JP; jp++) S[jp] = swap64(B[jp]);
            #pragma unroll
            for (int ip = 0; ip < 4; ip++)
                #pragma unroll
                for (int jp = 0; jp < JP; jp++) {
                    fma2(accN[ip][jp], A[ip], B[jp]);
                    fma2(accX[ip][jp], A[ip], S[jp]);
                }
        }
        __syncthreads();
    }

    float c[8][TN];
    #pragma unroll
    for (int ip = 0; ip < 4; ip++)
        #pragma unroll
        for (int jp = 0; jp < JP; jp++) {
            c[2 * ip + 0][2 * jp + 0] = lo32(accN[ip][jp]);
            c[2 * ip + 1][2 * jp + 1] = hi32(accN[ip][jp]);
            c[2 * ip + 0][2 * jp + 1] = lo32(accX[ip][jp]);
            c[2 * ip + 1][2 * jp + 0] = hi32(accX[ip][jp]);
        }

    #pragma unroll
    for (int i = 0; i < 8; i++) {
        int n = row0 + ty * 8 + i;
        if (n >= NN) continue;
        #pragma unroll
        for (int j = 0; j < TN; j += 4) {
            int h = tx * TN + j;
            float4 v;
            v.x = c[i][j + 0] + bias[h + 0];
            v.y = c[i][j + 1] + bias[h + 1];
            v.z = c[i][j + 2] + bias[h + 2];
            v.w = c[i][j + 3] + bias[h + 3];
            if (RELU) {
                v.x = fmaxf(v.x, 0.f); v.y = fmaxf(v.y, 0.f);
                v.z = fmaxf(v.z, 0.f); v.w = fmaxf(v.w, 0.f);
            }
            *(float4*)(out + (size_t)n * BN + h) = v;
        }
    }
}

// ---------------------------------------------------------------------------
// Launch
// ---------------------------------------------------------------------------
extern "C" void kernel_launch(void* const* d_in, const int* in_sizes, int n_in,
                              void* d_out, int out_size) {
    const float* x     = (const float*)d_in[0];
    const void*  ei    = d_in[1];
    const float* ew    = (const float*)d_in[2];
    const void*  et    = d_in[3];
    const float* W1    = (const float*)d_in[4];
    const float* root1 = (const float*)d_in[5];
    const float* bias1 = (const float*)d_in[6];
    const float* W2    = (const float*)d_in[7];
    const float* root2 = (const float*)d_in[8];
    const float* bias2 = (const float*)d_in[9];
    float* out = (float*)d_out;

    void *pT = nullptr, *ph = nullptr;
    cudaGetSymbolAddress(&pT, g_T);
    cudaGetSymbolAddress(&ph, g_h);
    const float* Tp = (const float*)pT;
    float*       hp = (float*)ph;

    k_detect<<<1, 1>>>(ei);
    k_zero_cnt<<<(NN + 255) / 256, 256>>>();
    k_edge_stats<<<1024, 256>>>(ei, ew);
    k_inv<<<(NN + 255) / 256, 256>>>();

    const size_t Tbytes = (size_t)NN * KT * sizeof(float);

    // ---- layer 1 ----
    cudaMemsetAsync(pT, 0, Tbytes);
    k_scatter<<<(EE * 32 + 255) / 256, 256>>>(x, ei, ew, et);
    k_gemm<128, 8, true><<<(NN + 127) / 128, 256>>>(Tp, W1, x, root1, bias1, hp);

    // ---- layer 2 ----
    cudaMemsetAsync(pT, 0, Tbytes);
    k_scatter<<<(EE * 32 + 255) / 256, 256>>>(hp, ei, ew, et);
    k_gemm<64, 4, false><<<(NN + 127) / 128, 256>>>(Tp, W2, hp, root2, bias2, out);
}

// round 5
// speedup vs baseline: 1.8220x; 1.4676x over previous
#include <cuda_runtime.h>
#include <stdint.h>

// Problem constants
#define NN 50000
#define EE 600000
#define FF 128
#define HH 128
#define OO 64
#define RR 8
#define NB1 ((NN + 1023) / 1024)   // 49 scan blocks

// ---------------------------------------------------------------------------
// Device scratch
// ---------------------------------------------------------------------------
__device__ float    g_Y[(size_t)NN * RR * HH];  // 204.8 MB projection buffer
__device__ float    g_h[(size_t)NN * HH];       // layer-1 output
__device__ int      g_bcnt[NN];                 // per-dst histogram
__device__ int      g_bcur[NN];                 // reorder cursors
__device__ int      g_boff[NN + 1];             // exclusive offsets (+ total)
__device__ int      g_part[64];                 // scan partials
__device__ int2     g_emeta[EE];                // sorted: {src*8+r, coef bits}
__device__ unsigned g_mm[2];                    // min/max bits of edge_weight
__device__ int      g_is64;

// ---------------------------------------------------------------------------
// Helpers
// ---------------------------------------------------------------------------
__device__ __forceinline__ int load_idx(const void* p, size_t i) {
    return g_is64 ? (int)((const long long*)p)[i] : ((const int*)p)[i];
}
__device__ __forceinline__ void fma2(unsigned long long& d,
                                     unsigned long long a,
                                     unsigned long long b) {
    asm("fma.rn.f32x2 %0, %1, %2, %0;" : "+l"(d) : "l"(a), "l"(b));
}
__device__ __forceinline__ unsigned long long swap64(unsigned long long v) {
    return (v >> 32) | (v << 32);
}
__device__ __forceinline__ float lo32(unsigned long long v) {
    return __uint_as_float((unsigned)v);
}
__device__ __forceinline__ float hi32(unsigned long long v) {
    return __uint_as_float((unsigned)(v >> 32));
}

// Detect index dtype: int64 values < 2^31 have zero odd 32-bit words.
__global__ void k_detect(const void* ei) {
    const int* p = (const int*)ei;
    int nz = 0;
    for (int i = 1; i < 2001; i += 2) nz |= p[i];
    g_is64 = (nz == 0) ? 1 : 0;
}

__global__ void k_zero() {
    int i = blockIdx.x * blockDim.x + threadIdx.x;
    for (int j = i; j < NN; j += gridDim.x * blockDim.x) {
        g_bcnt[j] = 0; g_bcur[j] = 0;
    }
    if (i == 0) { g_mm[0] = 0xFFFFFFFFu; g_mm[1] = 0u; }
}

// Histogram by dst + edge-weight min/max.
__global__ void k_hist(const void* __restrict__ ei,
                       const float* __restrict__ ew) {
    __shared__ unsigned smn, smx;
    if (threadIdx.x == 0) { smn = 0xFFFFFFFFu; smx = 0u; }
    __syncthreads();
    unsigned mn = 0xFFFFFFFFu, mx = 0u;
    for (int e = blockIdx.x * blockDim.x + threadIdx.x; e < EE;
         e += gridDim.x * blockDim.x) {
        unsigned b = __float_as_uint(ew[e]);
        mn = min(mn, b); mx = max(mx, b);
        int dst = load_idx(ei, (size_t)EE + e);
        atomicAdd(&g_bcnt[dst], 1);
    }
    #pragma unroll
    for (int o = 16; o; o >>= 1) {
        mn = min(mn, __shfl_xor_sync(0xFFFFFFFFu, mn, o));
        mx = max(mx, __shfl_xor_sync(0xFFFFFFFFu, mx, o));
    }
    if ((threadIdx.x & 31) == 0) { atomicMin(&smn, mn); atomicMax(&smx, mx); }
    __syncthreads();
    if (threadIdx.x == 0) { atomicMin(&g_mm[0], smn); atomicMax(&g_mm[1], smx); }
}

// Two-level exclusive scan of g_bcnt -> g_boff.
__global__ void k_scan1() {
    __shared__ int s[1024];
    int i = blockIdx.x * 1024 + threadIdx.x;
    int v = (i < NN) ? g_bcnt[i] : 0;
    s[threadIdx.x] = v;
    __syncthreads();
    for (int o = 1; o < 1024; o <<= 1) {
        int t = (threadIdx.x >= o) ? s[threadIdx.x - o] : 0;
        __syncthreads();
        s[threadIdx.x] += t;
        __syncthreads();
    }
    if (i < NN) g_boff[i] = s[threadIdx.x] - v;
    if (threadIdx.x == 1023) g_part[blockIdx.x] = s[1023];
}
__global__ void k_scan2() {
    __shared__ int s[64];
    int v = (threadIdx.x < NB1) ? g_part[threadIdx.x] : 0;
    s[threadIdx.x] = v;
    __syncthreads();
    for (int o = 1; o < 64; o <<= 1) {
        int t = (threadIdx.x >= o) ? s[threadIdx.x - o] : 0;
        __syncthreads();
        s[threadIdx.x] += t;
        __syncthreads();
    }
    if (threadIdx.x < NB1) g_part[threadIdx.x] = s[threadIdx.x] - v;
}
__global__ void k_scan3() {
    int i = blockIdx.x * blockDim.x + threadIdx.x;
    for (int j = i; j < NN; j += gridDim.x * blockDim.x)
        g_boff[j] += g_part[j >> 10];
    if (i == 0) g_boff[NN] = EE;
}

// Counting-sort by dst; meta = {src*8 + rel, coef = norm(ew) / cnt(dst)}.
__global__ void k_reorder(const void* __restrict__ ei,
                          const float* __restrict__ ew,
                          const void* __restrict__ et) {
    float mn = __uint_as_float(g_mm[0]);
    float mx = __uint_as_float(g_mm[1]);
    float sc = 1.0f / (mx - mn + 1e-8f);
    for (int e = blockIdx.x * blockDim.x + threadIdx.x; e < EE;
         e += gridDim.x * blockDim.x) {
        int src = load_idx(ei, e);
        int dst = load_idx(ei, (size_t)EE + e);
        int r   = load_idx(et, e);
        int cnt = g_boff[dst + 1] - g_boff[dst];
        int pos = g_boff[dst] + atomicAdd(&g_bcur[dst], 1);
        float coef = (ew[e] - mn) * sc / (float)max(cnt, 1);
        g_emeta[pos] = make_int2(src * RR + r, __float_as_int(coef));
    }
}

// ---------------------------------------------------------------------------
// Projection GEMM (packed fp32x2 FMA): C = A[N,128] @ B[blockIdx.y] (+ bias)
// B0 laid out as [gridDim.y][128][BN]; C row stride ldc, column base y*BN.
// ---------------------------------------------------------------------------
template <int BN, int TN, bool BIAS>
__global__ void __launch_bounds__(256, 2)
k_proj(const float* __restrict__ A, const float* __restrict__ B0,
       float* __restrict__ C, int ldc, const float* __restrict__ bias) {
    const int BM = 128, BK = 8;
    const int JP = TN / 2;
    __shared__ __align__(16) float As[BK][BM];
    __shared__ __align__(16) float Bs[BK][BN];
    int tid = threadIdx.x;
    int tx = tid & 15, ty = tid >> 4;
    int row0 = blockIdx.x * BM;
    const float* B = B0 + (size_t)blockIdx.y * FF * BN;
    int colbase = blockIdx.y * BN;

    unsigned long long accN[4][JP], accX[4][JP];
    #pragma unroll
    for (int i = 0; i < 4; i++)
        #pragma unroll
        for (int j = 0; j < JP; j++) { accN[i][j] = 0ull; accX[i][j] = 0ull; }

    int arow = tid >> 1, acol = (tid & 1) * 4;
    int n_a = row0 + arow;
    bool avalid = (n_a < NN);

    #pragma unroll 1
    for (int k0 = 0; k0 < FF; k0 += BK) {
        int ka = k0 + acol;
        float4 av = make_float4(0.f, 0.f, 0.f, 0.f);
        if (avalid) av = *(const float4*)(A + (size_t)n_a * FF + ka);
        As[acol + 0][arow] = av.x; As[acol + 1][arow] = av.y;
        As[acol + 2][arow] = av.z; As[acol + 3][arow] = av.w;
        if (BN == 128) {
            int brow = tid >> 5, bcol = (tid & 31) * 4;
            *(float4*)&Bs[brow][bcol] =
                *(const float4*)(B + (size_t)(k0 + brow) * BN + bcol);
        } else {
            int brow = tid >> 5, bcol = (tid & 31) * 2;
            *(float2*)&Bs[brow][bcol] =
                *(const float2*)(B + (size_t)(k0 + brow) * BN + bcol);
        }
        __syncthreads();

        #pragma unroll
        for (int kk = 0; kk < BK; kk++) {
            ulonglong2 a01 = *(ulonglong2*)&As[kk][ty * 8];
            ulonglong2 a23 = *(ulonglong2*)&As[kk][ty * 8 + 4];
            unsigned long long Ar[4] = {a01.x, a01.y, a23.x, a23.y};
            unsigned long long Br[JP], Sr[JP];
            if (TN == 8) {
                ulonglong2 b01 = *(ulonglong2*)&Bs[kk][tx * TN];
                ulonglong2 b23 = *(ulonglong2*)&Bs[kk][tx * TN + 4];
                Br[0] = b01.x; Br[1] = b01.y; Br[2] = b23.x; Br[3] = b23.y;
            } else {
                ulonglong2 b01 = *(ulonglong2*)&Bs[kk][tx * TN];
                Br[0] = b01.x; Br[1] = b01.y;
            }
            #pragma unroll
            for (int jp = 0; jp < JP; jp++) Sr[jp] = swap64(Br[jp]);
            #pragma unroll
            for (int ip = 0; ip < 4; ip++)
                #pragma unroll
                for (int jp = 0; jp < JP; jp++) {
                    fma2(accN[ip][jp], Ar[ip], Br[jp]);
                    fma2(accX[ip][jp], Ar[ip], Sr[jp]);
                }
        }
        __syncthreads();
    }

    float c[8][TN];
    #pragma unroll
    for (int ip = 0; ip < 4; ip++)
        #pragma unroll
        for (int jp = 0; jp < JP; jp++) {
            c[2 * ip + 0][2 * jp + 0] = lo32(accN[ip][jp]);
            c[2 * ip + 1][2 * jp + 1] = hi32(accN[ip][jp]);
            c[2 * ip + 0][2 * jp + 1] = lo32(accX[ip][jp]);
            c[2 * ip + 1][2 * jp + 0] = hi32(accX[ip][jp]);
        }

    #pragma unroll
    for (int i = 0; i < 8; i++) {
        int n = row0 + ty * 8 + i;
        if (n >= NN) continue;
        #pragma unroll
        for (int j = 0; j < TN; j += 4) {
            int h = tx * TN + j;
            float4 v;
            v.x = c[i][j + 0]; v.y = c[i][j + 1];
            v.z = c[i][j + 2]; v.w = c[i][j + 3];
            if (BIAS) {
                v.x += bias[h + 0]; v.y += bias[h + 1];
                v.z += bias[h + 2]; v.w += bias[h + 3];
            }
            *(float4*)(C + (size_t)n * ldc + colbase + h) = v;
        }
    }
}

// ---------------------------------------------------------------------------
// Gather-aggregate: one warp per dst node. C[d] += sum_e coef * Y[src*8+r];
// optional ReLU. C already holds x@root + bias.
// ---------------------------------------------------------------------------
template <int NH, bool RELU>
__global__ void k_agg(const float* __restrict__ Y, float* __restrict__ C) {
    int w = (blockIdx.x * blockDim.x + threadIdx.x) >> 5;
    int lane = threadIdx.x & 31;
    if (w >= NN) return;
    int s0 = g_boff[w], s1 = g_boff[w + 1];

    float a0 = 0.f, a1 = 0.f, a2 = 0.f, a3 = 0.f;
    for (int base = s0; base < s1; base += 32) {
        int idx = base + lane;
        int2 m = (idx < s1) ? g_emeta[idx] : make_int2(0, 0);
        int cnt = min(32, s1 - base);
        for (int j = 0; j < cnt; j++) {
            int sr   = __shfl_sync(0xFFFFFFFFu, m.x, j);
            float cf = __int_as_float(__shfl_sync(0xFFFFFFFFu, m.y, j));
            if (NH == 128) {
                float4 yv = *(const float4*)(Y + (size_t)sr * 128 + lane * 4);
                a0 += cf * yv.x; a1 += cf * yv.y;
                a2 += cf * yv.z; a3 += cf * yv.w;
            } else {
                float2 yv = *(const float2*)(Y + (size_t)sr * 64 + lane * 2);
                a0 += cf * yv.x; a1 += cf * yv.y;
            }
        }
    }

    if (NH == 128) {
        float4* cp = (float4*)(C + (size_t)w * 128 + lane * 4);
        float4 cv = *cp;
        cv.x += a0; cv.y += a1; cv.z += a2; cv.w += a3;
        if (RELU) {
            cv.x = fmaxf(cv.x, 0.f); cv.y = fmaxf(cv.y, 0.f);
            cv.z = fmaxf(cv.z, 0.f); cv.w = fmaxf(cv.w, 0.f);
        }
        *cp = cv;
    } else {
        float2* cp = (float2*)(C + (size_t)w * 64 + lane * 2);
        float2 cv = *cp;
        cv.x += a0; cv.y += a1;
        if (RELU) { cv.x = fmaxf(cv.x, 0.f); cv.y = fmaxf(cv.y, 0.f); }
        *cp = cv;
    }
}

// ---------------------------------------------------------------------------
// Launch
// ---------------------------------------------------------------------------
extern "C" void kernel_launch(void* const* d_in, const int* in_sizes, int n_in,
                              void* d_out, int out_size) {
    const float* x     = (const float*)d_in[0];
    const void*  ei    = d_in[1];
    const float* ew    = (const float*)d_in[2];
    const void*  et    = d_in[3];
    const float* W1    = (const float*)d_in[4];
    const float* root1 = (const float*)d_in[5];
    const float* bias1 = (const float*)d_in[6];
    const float* W2    = (const float*)d_in[7];
    const float* root2 = (const float*)d_in[8];
    const float* bias2 = (const float*)d_in[9];
    float* out = (float*)d_out;

    void *pY = nullptr, *ph = nullptr;
    cudaGetSymbolAddress(&pY, g_Y);
    cudaGetSymbolAddress(&ph, g_h);
    const float* Yp = (const float*)pY;
    float*       Ym = (float*)pY;
    float*       hp = (float*)ph;

    const int GB = (NN + 127) / 128;   // 391 row blocks
    const int GA = (NN * 32 + 255) / 256;

    k_detect<<<1, 1>>>(ei);                                     // #1
    k_zero<<<256, 256>>>();                                     // #2
    k_hist<<<1024, 256>>>(ei, ew);                              // #3
    // Y1 = x @ W1[r]  (independent of edge prep -> profiled slot #4)
    k_proj<128, 8, false><<<dim3(GB, RR), 256>>>(x, W1, Ym, RR * HH, nullptr);
    k_scan1<<<NB1, 1024>>>();                                   // #5
    k_scan2<<<1, 64>>>();                                       // #6
    k_scan3<<<256, 256>>>();                                    // #7
    k_reorder<<<1024, 256>>>(ei, ew, et);                       // #8

    // ---- layer 1: h = relu(agg(Y1) + x@root1 + bias1) ----
    k_proj<128, 8, true><<<dim3(GB, 1), 256>>>(x, root1, hp, HH, bias1);
    k_agg<128, true><<<GA, 256>>>(Yp, hp);

    // ---- layer 2: out = agg(Y2) + h@root2 + bias2 ----
    k_proj<64, 4, false><<<dim3(GB, RR), 256>>>(hp, W2, Ym, RR * OO, nullptr);
    k_proj<64, 4, true><<<dim3(GB, 1), 256>>>(hp, root2, out, OO, bias2);
    k_agg<64, false><<<GA, 256>>>(Yp, out);
}

// round 10
// speedup vs baseline: 2.5363x; 1.3921x over previous
#include <cuda_runtime.h>
#include <cuda_bf16.h>
#include <stdint.h>

// Problem constants
#define NN 50000
#define EE 600000
#define FF 128
#define HH 128
#define OO 64
#define RR 8
#define NB1 ((NN + 1023) / 1024)   // 49 scan blocks

// ---------------------------------------------------------------------------
// Device scratch
// ---------------------------------------------------------------------------
__device__ float          g_Y[(size_t)NN * RR * HH];  // projection buffer
__device__ float          g_h[(size_t)NN * HH];       // layer-1 output
__device__ __nv_bfloat16  g_Ah[(size_t)NN * FF];      // A hi plane
__device__ __nv_bfloat16  g_Al[(size_t)NN * FF];      // A lo plane
__device__ __nv_bfloat16  g_Wh[RR * FF * HH + FF * HH];  // W hi plane(s)
__device__ __nv_bfloat16  g_Wl[RR * FF * HH + FF * HH];  // W lo plane(s)
__device__ int            g_bcnt[NN];
__device__ int            g_bcur[NN];
__device__ int            g_boff[NN + 1];
__device__ int            g_part[64];
__device__ int2           g_emeta[EE];                // sorted: {src*8+r, coef}
__device__ unsigned       g_mm[2];
__device__ int            g_is64;

// ---------------------------------------------------------------------------
// Helpers
// ---------------------------------------------------------------------------
__device__ __forceinline__ int load_idx(const void* p, size_t i) {
    return g_is64 ? (int)((const long long*)p)[i] : ((const int*)p)[i];
}
__device__ __forceinline__ uint32_t smem_u32(const void* p) {
    uint32_t a;
    asm("{ .reg .u64 t; cvta.to.shared.u64 t, %1; cvt.u32.u64 %0, t; }"
        : "=r"(a) : "l"(p));
    return a;
}
__device__ __forceinline__ void ldsm_x4(uint32_t& r0, uint32_t& r1,
                                        uint32_t& r2, uint32_t& r3, uint32_t a) {
    asm volatile("ldmatrix.sync.aligned.m8n8.x4.shared.b16 {%0,%1,%2,%3}, [%4];"
                 : "=r"(r0), "=r"(r1), "=r"(r2), "=r"(r3) : "r"(a));
}
__device__ __forceinline__ void ldsm_x4t(uint32_t& r0, uint32_t& r1,
                                         uint32_t& r2, uint32_t& r3, uint32_t a) {
    asm volatile("ldmatrix.sync.aligned.m8n8.x4.trans.shared.b16 {%0,%1,%2,%3}, [%4];"
                 : "=r"(r0), "=r"(r1), "=r"(r2), "=r"(r3) : "r"(a));
}
__device__ __forceinline__ void mma_bf16(float* c, const uint32_t* a,
                                         uint32_t b0, uint32_t b1) {
    asm volatile(
        "mma.sync.aligned.m16n8k16.row.col.f32.bf16.bf16.f32 "
        "{%0,%1,%2,%3}, {%4,%5,%6,%7}, {%8,%9}, {%0,%1,%2,%3};"
        : "+f"(c[0]), "+f"(c[1]), "+f"(c[2]), "+f"(c[3])
        : "r"(a[0]), "r"(a[1]), "r"(a[2]), "r"(a[3]), "r"(b0), "r"(b1));
}

// ---------------------------------------------------------------------------
// Split fp32 -> bf16 hi/lo planes (n4 = element count / 4)
// ---------------------------------------------------------------------------
__global__ void k_split(const float* __restrict__ src,
                        __nv_bfloat16* __restrict__ hi,
                        __nv_bfloat16* __restrict__ lo, int n4) {
    int i = blockIdx.x * blockDim.x + threadIdx.x;
    if (i >= n4) return;
    float4 v = ((const float4*)src)[i];
    unsigned short h[4], l[4];
    float vs[4] = {v.x, v.y, v.z, v.w};
    #pragma unroll
    for (int j = 0; j < 4; j++) {
        __nv_bfloat16 b1 = __float2bfloat16(vs[j]);
        __nv_bfloat16 b2 = __float2bfloat16(vs[j] - __bfloat162float(b1));
        h[j] = __bfloat16_as_ushort(b1);
        l[j] = __bfloat16_as_ushort(b2);
    }
    uint2 ph, pl;
    ph.x = (uint32_t)h[0] | ((uint32_t)h[1] << 16);
    ph.y = (uint32_t)h[2] | ((uint32_t)h[3] << 16);
    pl.x = (uint32_t)l[0] | ((uint32_t)l[1] << 16);
    pl.y = (uint32_t)l[2] | ((uint32_t)l[3] << 16);
    ((uint2*)hi)[i] = ph;
    ((uint2*)lo)[i] = pl;
}

// ---------------------------------------------------------------------------
// Edge preprocessing (unchanged from round 5)
// ---------------------------------------------------------------------------
__global__ void k_detect(const void* ei) {
    const int* p = (const int*)ei;
    int nz = 0;
    for (int i = 1; i < 2001; i += 2) nz |= p[i];
    g_is64 = (nz == 0) ? 1 : 0;
}
__global__ void k_zero() {
    int i = blockIdx.x * blockDim.x + threadIdx.x;
    for (int j = i; j < NN; j += gridDim.x * blockDim.x) { g_bcnt[j] = 0; g_bcur[j] = 0; }
    if (i == 0) { g_mm[0] = 0xFFFFFFFFu; g_mm[1] = 0u; }
}
__global__ void k_hist(const void* __restrict__ ei, const float* __restrict__ ew) {
    __shared__ unsigned smn, smx;
    if (threadIdx.x == 0) { smn = 0xFFFFFFFFu; smx = 0u; }
    __syncthreads();
    unsigned mn = 0xFFFFFFFFu, mx = 0u;
    for (int e = blockIdx.x * blockDim.x + threadIdx.x; e < EE; e += gridDim.x * blockDim.x) {
        unsigned b = __float_as_uint(ew[e]);
        mn = min(mn, b); mx = max(mx, b);
        atomicAdd(&g_bcnt[load_idx(ei, (size_t)EE + e)], 1);
    }
    #pragma unroll
    for (int o = 16; o; o >>= 1) {
        mn = min(mn, __shfl_xor_sync(0xFFFFFFFFu, mn, o));
        mx = max(mx, __shfl_xor_sync(0xFFFFFFFFu, mx, o));
    }
    if ((threadIdx.x & 31) == 0) { atomicMin(&smn, mn); atomicMax(&smx, mx); }
    __syncthreads();
    if (threadIdx.x == 0) { atomicMin(&g_mm[0], smn); atomicMax(&g_mm[1], smx); }
}
__global__ void k_scan1() {
    __shared__ int s[1024];
    int i = blockIdx.x * 1024 + threadIdx.x;
    int v = (i < NN) ? g_bcnt[i] : 0;
    s[threadIdx.x] = v;
    __syncthreads();
    for (int o = 1; o < 1024; o <<= 1) {
        int t = (threadIdx.x >= o) ? s[threadIdx.x - o] : 0;
        __syncthreads();
        s[threadIdx.x] += t;
        __syncthreads();
    }
    if (i < NN) g_boff[i] = s[threadIdx.x] - v;
    if (threadIdx.x == 1023) g_part[blockIdx.x] = s[1023];
}
__global__ void k_scan2() {
    __shared__ int s[64];
    int v = (threadIdx.x < NB1) ? g_part[threadIdx.x] : 0;
    s[threadIdx.x] = v;
    __syncthreads();
    for (int o = 1; o < 64; o <<= 1) {
        int t = (threadIdx.x >= o) ? s[threadIdx.x - o] : 0;
        __syncthreads();
        s[threadIdx.x] += t;
        __syncthreads();
    }
    if (threadIdx.x < NB1) g_part[threadIdx.x] = s[threadIdx.x] - v;
}
__global__ void k_scan3() {
    int i = blockIdx.x * blockDim.x + threadIdx.x;
    for (int j = i; j < NN; j += gridDim.x * blockDim.x)
        g_boff[j] += g_part[j >> 10];
    if (i == 0) g_boff[NN] = EE;
}
__global__ void k_reorder(const void* __restrict__ ei, const float* __restrict__ ew,
                          const void* __restrict__ et) {
    float mn = __uint_as_float(g_mm[0]);
    float mx = __uint_as_float(g_mm[1]);
    float sc = 1.0f / (mx - mn + 1e-8f);
    for (int e = blockIdx.x * blockDim.x + threadIdx.x; e < EE; e += gridDim.x * blockDim.x) {
        int src = load_idx(ei, e);
        int dst = load_idx(ei, (size_t)EE + e);
        int r   = load_idx(et, e);
        int cnt = g_boff[dst + 1] - g_boff[dst];
        int pos = g_boff[dst] + atomicAdd(&g_bcur[dst], 1);
        float coef = (ew[e] - mn) * sc / (float)max(cnt, 1);
        g_emeta[pos] = make_int2(src * RR + r, __float_as_int(coef));
    }
}

// ---------------------------------------------------------------------------
// mma.sync split-bf16 GEMM.
// C[n, z*64 + c] = sum_k A[n,k] * B[k, z*64+c] (+ bias)
// A from bf16 hi/lo planes [N,128]; B from bf16 hi/lo planes, ldb row stride.
// BM=128, BN=64, K=128 in 2 chunks of 64. 256 threads = 8 warps,
// warp w owns rows [w*16, w*16+16) x all 64 cols (8 n8 tiles).
// 3-term split: a1*b1 + a2*b1 + a1*b2.
// ---------------------------------------------------------------------------
#define PK 72   // padded row width (halves) for sA
#define PN 72   // padded row width (halves) for sB

template <bool BIAS>
__global__ void __launch_bounds__(256)
tc_gemm(const __nv_bfloat16* __restrict__ Ah, const __nv_bfloat16* __restrict__ Al,
        const __nv_bfloat16* __restrict__ Bh0, const __nv_bfloat16* __restrict__ Bl0,
        long strideB, int ldb,
        float* __restrict__ C, long strideCy, int ldc,
        const float* __restrict__ bias) {
    extern __shared__ char smem[];
    __nv_bfloat16* sAh = (__nv_bfloat16*)(smem);
    __nv_bfloat16* sAl = (__nv_bfloat16*)(smem + 128 * PK * 2);
    __nv_bfloat16* sBh = (__nv_bfloat16*)(smem + 128 * PK * 4);
    __nv_bfloat16* sBl = (__nv_bfloat16*)(smem + 128 * PK * 4 + 64 * PN * 2);

    int tid = threadIdx.x, wid = tid >> 5, lane = tid & 31;
    int row0 = blockIdx.x * 128;
    long boff = (long)blockIdx.y * strideB + blockIdx.z * 64;
    const __nv_bfloat16* Bh = Bh0 + boff;
    const __nv_bfloat16* Bl = Bl0 + boff;
    float* Cw = C + (long)blockIdx.y * strideCy + blockIdx.z * 64;

    float acc[8][4];
    #pragma unroll
    for (int i = 0; i < 8; i++)
        #pragma unroll
        for (int j = 0; j < 4; j++) acc[i][j] = 0.f;

    int ar = tid >> 1, ac = (tid & 1) * 32;        // A: row, 32-half chunk
    bool av = (row0 + ar) < NN;
    int bk = tid >> 2, bn = (tid & 3) * 16;        // B: k-row, 16-half chunk

    int r = lane & 7, j = lane >> 3;               // ldmatrix lane decomposition

    #pragma unroll
    for (int ch = 0; ch < 2; ch++) {
        int k0g = ch * 64;
        // ---- A tiles: 32 halves per thread per plane (4 x uint4) ----
        {
            const uint4* pAh = (const uint4*)(Ah + (size_t)(row0 + ar) * FF + k0g + ac);
            const uint4* pAl = (const uint4*)(Al + (size_t)(row0 + ar) * FF + k0g + ac);
            uint4 z4 = make_uint4(0, 0, 0, 0);
            #pragma unroll
            for (int i = 0; i < 4; i++) {
                uint4 vh = av ? pAh[i] : z4;
                uint4 vl = av ? pAl[i] : z4;
                *(uint4*)&sAh[ar * PK + ac + i * 8] = vh;
                *(uint4*)&sAl[ar * PK + ac + i * 8] = vl;
            }
        }
        // ---- B tiles: 16 halves per thread per plane (2 x uint4) ----
        {
            const uint4* pBh = (const uint4*)(Bh + (size_t)(k0g + bk) * ldb + bn);
            const uint4* pBl = (const uint4*)(Bl + (size_t)(k0g + bk) * ldb + bn);
            #pragma unroll
            for (int i = 0; i < 2; i++) {
                *(uint4*)&sBh[bk * PN + bn + i * 8] = pBh[i];
                *(uint4*)&sBl[bk * PN + bn + i * 8] = pBl[i];
            }
        }
        __syncthreads();

        #pragma unroll
        for (int ks = 0; ks < 4; ks++) {
            int k0 = ks * 16;
            // A fragments: x4 covering (m..m+16, k0..k0+16).
            // lane -> matrix row r, matrix id j: addr (m + r + 8*(j&1), k0 + 8*(j>>1))
            uint32_t ah[4], al[4];
            int amrow = wid * 16 + r + 8 * (j & 1);
            int akcol = k0 + 8 * (j >> 1);
            ldsm_x4(ah[0], ah[1], ah[2], ah[3], smem_u32(&sAh[amrow * PK + akcol]));
            ldsm_x4(al[0], al[1], al[2], al[3], smem_u32(&sAl[amrow * PK + akcol]));

            // B fragments: per n16 pair, x4.trans covering (k0..k0+16, n0..n0+16)
            // -> regs {b0(nA), b1(nA), b0(nB), b1(nB)}
            int bkrow = k0 + r + 8 * (j & 1);
            int bncol0 = 8 * (j >> 1);
            #pragma unroll
            for (int p = 0; p < 4; p++) {
                uint32_t bh0, bh1, bh2, bh3, bl0, bl1, bl2, bl3;
                uint32_t baddr_h = smem_u32(&sBh[bkrow * PN + p * 16 + bncol0]);
                uint32_t baddr_l = smem_u32(&sBl[bkrow * PN + p * 16 + bncol0]);
                ldsm_x4t(bh0, bh1, bh2, bh3, baddr_h);
                ldsm_x4t(bl0, bl1, bl2, bl3, baddr_l);
                // n-tile 2p
                mma_bf16(acc[2 * p + 0], ah, bh0, bh1);   // a1*b1
                mma_bf16(acc[2 * p + 0], al, bh0, bh1);   // a2*b1
                mma_bf16(acc[2 * p + 0], ah, bl0, bl1);   // a1*b2
                // n-tile 2p+1
                mma_bf16(acc[2 * p + 1], ah, bh2, bh3);
                mma_bf16(acc[2 * p + 1], al, bh2, bh3);
                mma_bf16(acc[2 * p + 1], ah, bl2, bl3);
            }
        }
        __syncthreads();
    }

    // ---- epilogue ----
    int orow = row0 + wid * 16 + lane / 4;
    int oc0 = 2 * (lane & 3);
    #pragma unroll
    for (int nt = 0; nt < 8; nt++) {
        int col = nt * 8 + oc0;
        float bx = 0.f, by = 0.f;
        if (BIAS) {
            int bcol = blockIdx.z * 64 + col;
            bx = bias[bcol]; by = bias[bcol + 1];
        }
        if (orow < NN) {
            float2 v = make_float2(acc[nt][0] + bx, acc[nt][1] + by);
            *(float2*)&Cw[(size_t)orow * ldc + col] = v;
        }
        if (orow + 8 < NN) {
            float2 v = make_float2(acc[nt][2] + bx, acc[nt][3] + by);
            *(float2*)&Cw[(size_t)(orow + 8) * ldc + col] = v;
        }
    }
}

// ---------------------------------------------------------------------------
// Gather-aggregate (unchanged): one warp per dst node.
// ---------------------------------------------------------------------------
template <int NH, bool RELU>
__global__ void k_agg(const float* __restrict__ Y, float* __restrict__ C) {
    int w = (blockIdx.x * blockDim.x + threadIdx.x) >> 5;
    int lane = threadIdx.x & 31;
    if (w >= NN) return;
    int s0 = g_boff[w], s1 = g_boff[w + 1];

    float a0 = 0.f, a1 = 0.f, a2 = 0.f, a3 = 0.f;
    for (int base = s0; base < s1; base += 32) {
        int idx = base + lane;
        int2 m = (idx < s1) ? g_emeta[idx] : make_int2(0, 0);
        int cnt = min(32, s1 - base);
        for (int jj = 0; jj < cnt; jj++) {
            int sr   = __shfl_sync(0xFFFFFFFFu, m.x, jj);
            float cf = __int_as_float(__shfl_sync(0xFFFFFFFFu, m.y, jj));
            if (NH == 128) {
                float4 yv = *(const float4*)(Y + (size_t)sr * 128 + lane * 4);
                a0 += cf * yv.x; a1 += cf * yv.y;
                a2 += cf * yv.z; a3 += cf * yv.w;
            } else {
                float2 yv = *(const float2*)(Y + (size_t)sr * 64 + lane * 2);
                a0 += cf * yv.x; a1 += cf * yv.y;
            }
        }
    }

    if (NH == 128) {
        float4* cp = (float4*)(C + (size_t)w * 128 + lane * 4);
        float4 cv = *cp;
        cv.x += a0; cv.y += a1; cv.z += a2; cv.w += a3;
        if (RELU) {
            cv.x = fmaxf(cv.x, 0.f); cv.y = fmaxf(cv.y, 0.f);
            cv.z = fmaxf(cv.z, 0.f); cv.w = fmaxf(cv.w, 0.f);
        }
        *cp = cv;
    } else {
        float2* cp = (float2*)(C + (size_t)w * 64 + lane * 2);
        float2 cv = *cp;
        cv.x += a0; cv.y += a1;
        if (RELU) { cv.x = fmaxf(cv.x, 0.f); cv.y = fmaxf(cv.y, 0.f); }
        *cp = cv;
    }
}

// ---------------------------------------------------------------------------
// Launch
// ---------------------------------------------------------------------------
extern "C" void kernel_launch(void* const* d_in, const int* in_sizes, int n_in,
                              void* d_out, int out_size) {
    const float* x     = (const float*)d_in[0];
    const void*  ei    = d_in[1];
    const float* ew    = (const float*)d_in[2];
    const void*  et    = d_in[3];
    const float* W1    = (const float*)d_in[4];
    const float* root1 = (const float*)d_in[5];
    const float* bias1 = (const float*)d_in[6];
    const float* W2    = (const float*)d_in[7];
    const float* root2 = (const float*)d_in[8];
    const float* bias2 = (const float*)d_in[9];
    float* out = (float*)d_out;

    void *pY, *ph, *pAh, *pAl, *pWh, *pWl;
    cudaGetSymbolAddress(&pY, g_Y);
    cudaGetSymbolAddress(&ph, g_h);
    cudaGetSymbolAddress(&pAh, g_Ah);
    cudaGetSymbolAddress(&pAl, g_Al);
    cudaGetSymbolAddress(&pWh, g_Wh);
    cudaGetSymbolAddress(&pWl, g_Wl);
    const float* Yp = (const float*)pY;
    float*       Ym = (float*)pY;
    float*       hp = (float*)ph;
    __nv_bfloat16* Ah = (__nv_bfloat16*)pAh;
    __nv_bfloat16* Al = (__nv_bfloat16*)pAl;
    __nv_bfloat16* Wh = (__nv_bfloat16*)pWh;
    __nv_bfloat16* Wl = (__nv_bfloat16*)pWl;

    const int GB = (NN + 127) / 128;   // 391 row tiles
    const int GA = (NN * 32 + 255) / 256;
    const int SMEM = 128 * PK * 2 * 2 + 64 * PN * 2 * 2;  // 55296 bytes
    cudaFuncSetAttribute(tc_gemm<false>, cudaFuncAttributeMaxDynamicSharedMemorySize, SMEM);
    cudaFuncSetAttribute(tc_gemm<true>,  cudaFuncAttributeMaxDynamicSharedMemorySize, SMEM);

    k_detect<<<1, 1>>>(ei);
    k_zero<<<256, 256>>>();
    k_hist<<<1024, 256>>>(ei, ew);

    // Split x and layer-1 weights into bf16 planes
    k_split<<<(NN * FF / 4 + 255) / 256, 256>>>(x, Ah, Al, NN * FF / 4);
    k_split<<<(RR * FF * HH / 4 + 255) / 256, 256>>>(W1, Wh, Wl, RR * FF * HH / 4);
    k_split<<<(FF * HH / 4 + 255) / 256, 256>>>(root1, Wh + RR * FF * HH,
                                                Wl + RR * FF * HH, FF * HH / 4);
    // Y1 = x @ W1[r]  -> Y[n*8+r][0..128)
    tc_gemm<false><<<dim3(GB, RR, 2), 256, SMEM>>>(
        Ah, Al, Wh, Wl, (long)FF * HH, HH, Ym, (long)HH, RR * HH, nullptr);

    k_scan1<<<NB1, 1024>>>();
    k_scan2<<<1, 64>>>();
    k_scan3<<<256, 256>>>();
    k_reorder<<<1024, 256>>>(ei, ew, et);

    // h = x @ root1 + bias1
    tc_gemm<true><<<dim3(GB, 1, 2), 256, SMEM>>>(
        Ah, Al, Wh + RR * FF * HH, Wl + RR * FF * HH, 0L, HH, hp, 0L, HH, bias1);
    // h += agg(Y1); relu
    k_agg<128, true><<<GA, 256>>>(Yp, hp);

    // Split h and layer-2 weights
    k_split<<<(NN * HH / 4 + 255) / 256, 256>>>(hp, Ah, Al, NN * HH / 4);
    k_split<<<(RR * HH * OO / 4 + 255) / 256, 256>>>(W2, Wh, Wl, RR * HH * OO / 4);
    k_split<<<(HH * OO / 4 + 255) / 256, 256>>>(root2, Wh + RR * HH * OO,
                                                Wl + RR * HH * OO, HH * OO / 4);
    // Y2 = h @ W2[r]  -> Y[n*8+r][0..64)
    tc_gemm<false><<<dim3(GB, RR, 1), 256, SMEM>>>(
        Ah, Al, Wh, Wl, (long)HH * OO, OO, Ym, (long)OO, RR * OO, nullptr);
    // out = h @ root2 + bias2
    tc_gemm<true><<<dim3(GB, 1, 1), 256, SMEM>>>(
        Ah, Al, Wh + RR * HH * OO, Wl + RR * HH * OO, 0L, OO, out, 0L, OO, bias2);
    // out += agg(Y2)
    k_agg<64, false><<<GA, 256>>>(Yp, out);
}

// round 11
// speedup vs baseline: 3.5130x; 1.3851x over previous
#include <cuda_runtime.h>
#include <cuda_bf16.h>
#include <stdint.h>

// Problem constants
#define NN 50000
#define EE 600000
#define FF 128
#define HH 128
#define OO 64
#define RR 8
#define NS 9                       // 8 relations + root slot
#define NB1 ((NN + 1023) / 1024)   // 49 scan blocks

// ---------------------------------------------------------------------------
// Device scratch
// ---------------------------------------------------------------------------
__device__ float          g_Y[(size_t)NN * NS * HH];  // 230.4 MB projection buf
__device__ __nv_bfloat16  g_Ah[(size_t)NN * FF];      // A hi plane
__device__ __nv_bfloat16  g_Al[(size_t)NN * FF];      // A lo plane
__device__ __nv_bfloat16  g_Wh[NS * FF * HH];         // W hi (slots 0..8)
__device__ __nv_bfloat16  g_Wl[NS * FF * HH];         // W lo
__device__ int            g_bcnt[NN];
__device__ int            g_bcur[NN];
__device__ int            g_boff[NN + 1];
__device__ int            g_part[64];
__device__ int2           g_emeta[EE];                // sorted: {src*9+r, coef}
__device__ unsigned       g_mm[2];
__device__ int            g_is64;

// ---------------------------------------------------------------------------
// Helpers
// ---------------------------------------------------------------------------
__device__ __forceinline__ int load_idx(const void* p, size_t i) {
    return g_is64 ? (int)((const long long*)p)[i] : ((const int*)p)[i];
}
__device__ __forceinline__ uint32_t smem_u32(const void* p) {
    uint32_t a;
    asm("{ .reg .u64 t; cvta.to.shared.u64 t, %1; cvt.u32.u64 %0, t; }"
        : "=r"(a) : "l"(p));
    return a;
}
__device__ __forceinline__ void cp16(uint32_t d, const void* s, uint32_t nbytes) {
    asm volatile("cp.async.cg.shared.global [%0], [%1], 16, %2;"
                 :: "r"(d), "l"(s), "r"(nbytes) : "memory");
}
__device__ __forceinline__ void ldsm_x4(uint32_t& r0, uint32_t& r1,
                                        uint32_t& r2, uint32_t& r3, uint32_t a) {
    asm volatile("ldmatrix.sync.aligned.m8n8.x4.shared.b16 {%0,%1,%2,%3}, [%4];"
                 : "=r"(r0), "=r"(r1), "=r"(r2), "=r"(r3) : "r"(a));
}
__device__ __forceinline__ void ldsm_x4t(uint32_t& r0, uint32_t& r1,
                                         uint32_t& r2, uint32_t& r3, uint32_t a) {
    asm volatile("ldmatrix.sync.aligned.m8n8.x4.trans.shared.b16 {%0,%1,%2,%3}, [%4];"
                 : "=r"(r0), "=r"(r1), "=r"(r2), "=r"(r3) : "r"(a));
}
__device__ __forceinline__ void mma_bf16(float* c, const uint32_t* a,
                                         uint32_t b0, uint32_t b1) {
    asm volatile(
        "mma.sync.aligned.m16n8k16.row.col.f32.bf16.bf16.f32 "
        "{%0,%1,%2,%3}, {%4,%5,%6,%7}, {%8,%9}, {%0,%1,%2,%3};"
        : "+f"(c[0]), "+f"(c[1]), "+f"(c[2]), "+f"(c[3])
        : "r"(a[0]), "r"(a[1]), "r"(a[2]), "r"(a[3]), "r"(b0), "r"(b1));
}
__device__ __forceinline__ void split1(float v, unsigned short& h, unsigned short& l) {
    __nv_bfloat16 b1 = __float2bfloat16(v);
    __nv_bfloat16 b2 = __float2bfloat16(v - __bfloat162float(b1));
    h = __bfloat16_as_ushort(b1);
    l = __bfloat16_as_ushort(b2);
}

// ---------------------------------------------------------------------------
// Split fp32 -> bf16 hi/lo planes (n4 = element count / 4)
// ---------------------------------------------------------------------------
__global__ void k_split(const float* __restrict__ src,
                        __nv_bfloat16* __restrict__ hi,
                        __nv_bfloat16* __restrict__ lo, int n4) {
    int i = blockIdx.x * blockDim.x + threadIdx.x;
    if (i >= n4) return;
    float4 v = ((const float4*)src)[i];
    unsigned short h[4], l[4];
    float vs[4] = {v.x, v.y, v.z, v.w};
    #pragma unroll
    for (int j = 0; j < 4; j++) split1(vs[j], h[j], l[j]);
    uint2 ph, pl;
    ph.x = (uint32_t)h[0] | ((uint32_t)h[1] << 16);
    ph.y = (uint32_t)h[2] | ((uint32_t)h[3] << 16);
    pl.x = (uint32_t)l[0] | ((uint32_t)l[1] << 16);
    pl.y = (uint32_t)l[2] | ((uint32_t)l[3] << 16);
    ((uint2*)hi)[i] = ph;
    ((uint2*)lo)[i] = pl;
}

// ---------------------------------------------------------------------------
// Edge preprocessing
// ---------------------------------------------------------------------------
__global__ void k_detect(const void* ei) {
    const int* p = (const int*)ei;
    int nz = 0;
    for (int i = 1; i < 2001; i += 2) nz |= p[i];
    g_is64 = (nz == 0) ? 1 : 0;
}
__global__ void k_zero() {
    int i = blockIdx.x * blockDim.x + threadIdx.x;
    for (int j = i; j < NN; j += gridDim.x * blockDim.x) { g_bcnt[j] = 0; g_bcur[j] = 0; }
    if (i == 0) { g_mm[0] = 0xFFFFFFFFu; g_mm[1] = 0u; }
}
__global__ void k_hist(const void* __restrict__ ei, const float* __restrict__ ew) {
    __shared__ unsigned smn, smx;
    if (threadIdx.x == 0) { smn = 0xFFFFFFFFu; smx = 0u; }
    __syncthreads();
    unsigned mn = 0xFFFFFFFFu, mx = 0u;
    for (int e = blockIdx.x * blockDim.x + threadIdx.x; e < EE; e += gridDim.x * blockDim.x) {
        unsigned b = __float_as_uint(ew[e]);
        mn = min(mn, b); mx = max(mx, b);
        atomicAdd(&g_bcnt[load_idx(ei, (size_t)EE + e)], 1);
    }
    #pragma unroll
    for (int o = 16; o; o >>= 1) {
        mn = min(mn, __shfl_xor_sync(0xFFFFFFFFu, mn, o));
        mx = max(mx, __shfl_xor_sync(0xFFFFFFFFu, mx, o));
    }
    if ((threadIdx.x & 31) == 0) { atomicMin(&smn, mn); atomicMax(&smx, mx); }
    __syncthreads();
    if (threadIdx.x == 0) { atomicMin(&g_mm[0], smn); atomicMax(&g_mm[1], smx); }
}
__global__ void k_scan1() {
    __shared__ int s[1024];
    int i = blockIdx.x * 1024 + threadIdx.x;
    int v = (i < NN) ? g_bcnt[i] : 0;
    s[threadIdx.x] = v;
    __syncthreads();
    for (int o = 1; o < 1024; o <<= 1) {
        int t = (threadIdx.x >= o) ? s[threadIdx.x - o] : 0;
        __syncthreads();
        s[threadIdx.x] += t;
        __syncthreads();
    }
    if (i < NN) g_boff[i] = s[threadIdx.x] - v;
    if (threadIdx.x == 1023) g_part[blockIdx.x] = s[1023];
}
__global__ void k_scan2() {
    __shared__ int s[64];
    int v = (threadIdx.x < NB1) ? g_part[threadIdx.x] : 0;
    s[threadIdx.x] = v;
    __syncthreads();
    for (int o = 1; o < 64; o <<= 1) {
        int t = (threadIdx.x >= o) ? s[threadIdx.x - o] : 0;
        __syncthreads();
        s[threadIdx.x] += t;
        __syncthreads();
    }
    if (threadIdx.x < NB1) g_part[threadIdx.x] = s[threadIdx.x] - v;
}
__global__ void k_scan3() {
    int i = blockIdx.x * blockDim.x + threadIdx.x;
    for (int j = i; j < NN; j += gridDim.x * blockDim.x)
        g_boff[j] += g_part[j >> 10];
    if (i == 0) g_boff[NN] = EE;
}
__global__ void k_reorder(const void* __restrict__ ei, const float* __restrict__ ew,
                          const void* __restrict__ et) {
    float mn = __uint_as_float(g_mm[0]);
    float mx = __uint_as_float(g_mm[1]);
    float sc = 1.0f / (mx - mn + 1e-8f);
    for (int e = blockIdx.x * blockDim.x + threadIdx.x; e < EE; e += gridDim.x * blockDim.x) {
        int src = load_idx(ei, e);
        int dst = load_idx(ei, (size_t)EE + e);
        int r   = load_idx(et, e);
        int cnt = g_boff[dst + 1] - g_boff[dst];
        int pos = g_boff[dst] + atomicAdd(&g_bcur[dst], 1);
        float coef = (ew[e] - mn) * sc / (float)max(cnt, 1);
        g_emeta[pos] = make_int2(src * NS + r, __float_as_int(coef));
    }
}

// ---------------------------------------------------------------------------
// mma.sync split-bf16 GEMM with async loads.
// C[n, y*cstride + z*64 + c] = sum_k A[n,k] * B_y[k, z*64+c]
// Full K=128 A tile + B tile loaded once via cp.async (24 deep), one sync,
// then 8 uninterrupted k16 steps. 3-term: a1*b1 + a2*b1 + a1*b2.
// ---------------------------------------------------------------------------
#define PKA 136   // A smem row width (halves): 128 + 8 pad -> 272B stride
#define PNB 72    // B smem row width (halves): 64 + 8 pad -> 144B stride
#define SM_A (128 * PKA * 2)            // 34816 B per plane
#define SM_B (128 * PNB * 2)            // 18432 B per plane
#define SMEM_GEMM (2 * SM_A + 2 * SM_B) // 106496 B

__global__ void __launch_bounds__(256, 2)
tc_gemm(const __nv_bfloat16* __restrict__ Ah, const __nv_bfloat16* __restrict__ Al,
        const __nv_bfloat16* __restrict__ Bh0, const __nv_bfloat16* __restrict__ Bl0,
        long strideB, int ldb, int cstride,
        float* __restrict__ C, int ldc) {
    extern __shared__ char smem[];
    __nv_bfloat16* sAh = (__nv_bfloat16*)(smem);
    __nv_bfloat16* sAl = (__nv_bfloat16*)(smem + SM_A);
    __nv_bfloat16* sBh = (__nv_bfloat16*)(smem + 2 * SM_A);
    __nv_bfloat16* sBl = (__nv_bfloat16*)(smem + 2 * SM_A + SM_B);

    int tid = threadIdx.x, wid = tid >> 5, lane = tid & 31;
    int row0 = blockIdx.x * 128;
    long boff = (long)blockIdx.y * strideB + blockIdx.z * 64;
    const __nv_bfloat16* Bh = Bh0 + boff;
    const __nv_bfloat16* Bl = Bl0 + boff;
    float* Cw = C + blockIdx.y * cstride + blockIdx.z * 64;

    uint32_t uAh = smem_u32(sAh), uAl = smem_u32(sAl);
    uint32_t uBh = smem_u32(sBh), uBl = smem_u32(sBl);

    // ---- async loads: A = 128 rows x 256B (16 chunks/row), both planes ----
    #pragma unroll
    for (int i = 0; i < 8; i++) {
        int c = tid + i * 256;
        int row = c >> 4, col = c & 15;
        int gr = row0 + row;
        uint32_t ok = (gr < NN) ? 16u : 0u;
        int grc = gr < NN ? gr : NN - 1;
        const char* srch = (const char*)(Ah + (size_t)grc * FF) + col * 16;
        const char* srcl = (const char*)(Al + (size_t)grc * FF) + col * 16;
        cp16(uAh + row * 272 + col * 16, srch, ok);
        cp16(uAl + row * 272 + col * 16, srcl, ok);
    }
    // ---- B = 128 k-rows x 128B (8 chunks/row), both planes ----
    #pragma unroll
    for (int i = 0; i < 4; i++) {
        int c = tid + i * 256;
        int row = c >> 3, col = c & 7;
        const char* srch = (const char*)(Bh + (size_t)row * ldb) + col * 16;
        const char* srcl = (const char*)(Bl + (size_t)row * ldb) + col * 16;
        cp16(uBh + row * 144 + col * 16, srch, 16u);
        cp16(uBl + row * 144 + col * 16, srcl, 16u);
    }
    asm volatile("cp.async.commit_group;" ::: "memory");
    asm volatile("cp.async.wait_group 0;" ::: "memory");
    __syncthreads();

    float acc[8][4];
    #pragma unroll
    for (int i = 0; i < 8; i++)
        #pragma unroll
        for (int j = 0; j < 4; j++) acc[i][j] = 0.f;

    int r = lane & 7, j = lane >> 3;

    #pragma unroll
    for (int ks = 0; ks < 8; ks++) {
        int k0 = ks * 16;
        uint32_t ah[4], al[4];
        int amrow = wid * 16 + r + 8 * (j & 1);
        int akcol = k0 + 8 * (j >> 1);
        ldsm_x4(ah[0], ah[1], ah[2], ah[3], uAh + (amrow * PKA + akcol) * 2);
        ldsm_x4(al[0], al[1], al[2], al[3], uAl + (amrow * PKA + akcol) * 2);

        int bkrow = k0 + r + 8 * (j & 1);
        int bncol0 = 8 * (j >> 1);
        #pragma unroll
        for (int p = 0; p < 4; p++) {
            uint32_t bh0, bh1, bh2, bh3, bl0, bl1, bl2, bl3;
            ldsm_x4t(bh0, bh1, bh2, bh3, uBh + (bkrow * PNB + p * 16 + bncol0) * 2);
            ldsm_x4t(bl0, bl1, bl2, bl3, uBl + (bkrow * PNB + p * 16 + bncol0) * 2);
            mma_bf16(acc[2 * p + 0], ah, bh0, bh1);   // a1*b1
            mma_bf16(acc[2 * p + 0], al, bh0, bh1);   // a2*b1
            mma_bf16(acc[2 * p + 0], ah, bl0, bl1);   // a1*b2
            mma_bf16(acc[2 * p + 1], ah, bh2, bh3);
            mma_bf16(acc[2 * p + 1], al, bh2, bh3);
            mma_bf16(acc[2 * p + 1], ah, bl2, bl3);
        }
    }

    // ---- epilogue ----
    int orow = row0 + wid * 16 + lane / 4;
    int oc0 = 2 * (lane & 3);
    #pragma unroll
    for (int nt = 0; nt < 8; nt++) {
        int col = nt * 8 + oc0;
        if (orow < NN)
            *(float2*)&Cw[(size_t)orow * ldc + col] =
                make_float2(acc[nt][0], acc[nt][1]);
        if (orow + 8 < NN)
            *(float2*)&Cw[(size_t)(orow + 8) * ldc + col] =
                make_float2(acc[nt][2], acc[nt][3]);
    }
}

// ---------------------------------------------------------------------------
// Layer-1 aggregate: h = relu(Y1[root slot] + bias + sum msgs), written
// directly as bf16 hi/lo planes (fused split). One warp per dst node.
// ---------------------------------------------------------------------------
__global__ void k_agg1(const float* __restrict__ Y, const float* __restrict__ bias,
                       __nv_bfloat16* __restrict__ hh, __nv_bfloat16* __restrict__ hl) {
    int w = (blockIdx.x * blockDim.x + threadIdx.x) >> 5;
    int lane = threadIdx.x & 31;
    if (w >= NN) return;
    int s0 = g_boff[w], s1 = g_boff[w + 1];

    float4 rv = *(const float4*)(Y + ((size_t)w * NS + 8) * HH + lane * 4);
    float4 bv = *(const float4*)(bias + lane * 4);
    float a0 = rv.x + bv.x, a1 = rv.y + bv.y, a2 = rv.z + bv.z, a3 = rv.w + bv.w;

    for (int base = s0; base < s1; base += 32) {
        int idx = base + lane;
        int2 m = (idx < s1) ? g_emeta[idx] : make_int2(0, 0);
        int cnt = min(32, s1 - base);
        for (int jj = 0; jj < cnt; jj++) {
            int sr   = __shfl_sync(0xFFFFFFFFu, m.x, jj);
            float cf = __int_as_float(__shfl_sync(0xFFFFFFFFu, m.y, jj));
            float4 yv = *(const float4*)(Y + (size_t)sr * HH + lane * 4);
            a0 += cf * yv.x; a1 += cf * yv.y; a2 += cf * yv.z; a3 += cf * yv.w;
        }
    }
    a0 = fmaxf(a0, 0.f); a1 = fmaxf(a1, 0.f);
    a2 = fmaxf(a2, 0.f); a3 = fmaxf(a3, 0.f);

    unsigned short h[4], l[4];
    split1(a0, h[0], l[0]); split1(a1, h[1], l[1]);
    split1(a2, h[2], l[2]); split1(a3, h[3], l[3]);
    uint2 ph, pl;
    ph.x = (uint32_t)h[0] | ((uint32_t)h[1] << 16);
    ph.y = (uint32_t)h[2] | ((uint32_t)h[3] << 16);
    pl.x = (uint32_t)l[0] | ((uint32_t)l[1] << 16);
    pl.y = (uint32_t)l[2] | ((uint32_t)l[3] << 16);
    ((uint2*)(hh + (size_t)w * FF))[lane] = ph;
    ((uint2*)(hl + (size_t)w * FF))[lane] = pl;
}

// ---------------------------------------------------------------------------
// Layer-2 aggregate: out = Y2[root slot] + bias + sum msgs (fp32 out).
// ---------------------------------------------------------------------------
__global__ void k_agg2(const float* __restrict__ Y, const float* __restrict__ bias,
                       float* __restrict__ out) {
    int w = (blockIdx.x * blockDim.x + threadIdx.x) >> 5;
    int lane = threadIdx.x & 31;
    if (w >= NN) return;
    int s0 = g_boff[w], s1 = g_boff[w + 1];

    float2 rv = *(const float2*)(Y + ((size_t)w * NS + 8) * OO + lane * 2);
    float a0 = rv.x + bias[lane * 2], a1 = rv.y + bias[lane * 2 + 1];

    for (int base = s0; base < s1; base += 32) {
        int idx = base + lane;
        int2 m = (idx < s1) ? g_emeta[idx] : make_int2(0, 0);
        int cnt = min(32, s1 - base);
        for (int jj = 0; jj < cnt; jj++) {
            int sr   = __shfl_sync(0xFFFFFFFFu, m.x, jj);
            float cf = __int_as_float(__shfl_sync(0xFFFFFFFFu, m.y, jj));
            float2 yv = *(const float2*)(Y + (size_t)sr * OO + lane * 2);
            a0 += cf * yv.x; a1 += cf * yv.y;
        }
    }
    *(float2*)&out[(size_t)w * OO + lane * 2] = make_float2(a0, a1);
}

// ---------------------------------------------------------------------------
// Launch
// ---------------------------------------------------------------------------
extern "C" void kernel_launch(void* const* d_in, const int* in_sizes, int n_in,
                              void* d_out, int out_size) {
    const float* x     = (const float*)d_in[0];
    const void*  ei    = d_in[1];
    const float* ew    = (const float*)d_in[2];
    const void*  et    = d_in[3];
    const float* W1    = (const float*)d_in[4];
    const float* root1 = (const float*)d_in[5];
    const float* bias1 = (const float*)d_in[6];
    const float* W2    = (const float*)d_in[7];
    const float* root2 = (const float*)d_in[8];
    const float* bias2 = (const float*)d_in[9];
    float* out = (float*)d_out;

    void *pY, *pAh, *pAl, *pWh, *pWl;
    cudaGetSymbolAddress(&pY, g_Y);
    cudaGetSymbolAddress(&pAh, g_Ah);
    cudaGetSymbolAddress(&pAl, g_Al);
    cudaGetSymbolAddress(&pWh, g_Wh);
    cudaGetSymbolAddress(&pWl, g_Wl);
    const float* Yp = (const float*)pY;
    float*       Ym = (float*)pY;
    __nv_bfloat16* Ah = (__nv_bfloat16*)pAh;
    __nv_bfloat16* Al = (__nv_bfloat16*)pAl;
    __nv_bfloat16* Wh = (__nv_bfloat16*)pWh;
    __nv_bfloat16* Wl = (__nv_bfloat16*)pWl;

    const int GB = (NN + 127) / 128;   // 391 row tiles
    const int GA = (NN * 32 + 255) / 256;
    cudaFuncSetAttribute(tc_gemm, cudaFuncAttributeMaxDynamicSharedMemorySize, SMEM_GEMM);

    k_detect<<<1, 1>>>(ei);                                          // 1
    k_zero<<<256, 256>>>();                                          // 2
    k_split<<<(NN * FF / 4 + 255) / 256, 256>>>(x, Ah, Al, NN * FF / 4);          // 3
    k_split<<<(RR * FF * HH / 4 + 255) / 256, 256>>>(W1, Wh, Wl, RR * FF * HH / 4);  // 4
    k_split<<<(FF * HH / 4 + 255) / 256, 256>>>(root1, Wh + RR * FF * HH,
                                                Wl + RR * FF * HH, FF * HH / 4);  // 5
    // Y1 (+root slot 8): grid (391, 9, 2), BN=64 halves of each 128-wide slot
    tc_gemm<<<dim3(GB, NS, 2), 256, SMEM_GEMM>>>(                    // 6 (profiled)
        Ah, Al, Wh, Wl, (long)FF * HH, HH, HH, Ym, NS * HH);

    k_hist<<<1024, 256>>>(ei, ew);                                   // 7
    k_scan1<<<NB1, 1024>>>();                                        // 8
    k_scan2<<<1, 64>>>();                                            // 9
    k_scan3<<<256, 256>>>();                                         // 10
    k_reorder<<<1024, 256>>>(ei, ew, et);                            // 11

    // h = relu(root + bias1 + agg) -> bf16 planes (fused split)
    k_agg1<<<GA, 256>>>(Yp, bias1, Ah, Al);                          // 12

    // layer-2 weights (+root slot 8)
    k_split<<<(RR * HH * OO / 4 + 255) / 256, 256>>>(W2, Wh, Wl, RR * HH * OO / 4);  // 13
    k_split<<<(HH * OO / 4 + 255) / 256, 256>>>(root2, Wh + RR * HH * OO,
                                                Wl + RR * HH * OO, HH * OO / 4);  // 14
    // Y2 (+root slot 8): grid (391, 9, 1), 64-wide slots
    tc_gemm<<<dim3(GB, NS, 1), 256, SMEM_GEMM>>>(                    // 15
        Ah, Al, Wh, Wl, (long)HH * OO, OO, OO, Ym, NS * OO);

    // out = root + bias2 + agg
    k_agg2<<<GA, 256>>>(Yp, bias2, out);                             // 16
}